// round 16
// baseline (speedup 1.0000x reference)
#include <cuda_runtime.h>
#include <math.h>
#include <stdint.h>

// ---------------- problem constants ----------------
#define B32    32
#define TENC   256
#define TDEC   512
#define NMELS  80
#define EDIM   512
#define PRE    256
#define HID    1024
#define ATT    128
#define LOCF   32
#define LOCK   31
#define KA     1792           // PRE + EDIM + HID  (x | ctx | ah)
#define KD     2560           // HID + EDIM + HID  (ah | ctx | dh)
#define R4     4096
#define NSPL   4
#define NBLK   128
#define NTHR   256

#define MEL_SZ    (B32*NMELS*TDEC)
#define GATE_OFF  MEL_SZ
#define ALIGN_OFF (MEL_SZ + B32*TDEC)

// frag smem offsets (floats): A-frags [8 mb][4 kb][32 lane][4] = 4096, B-frags [4 kb][4 nt][32 lane][2] = 1024
#define SH_BFRAG 4096

// ---------------- static device buffers ----------------
__device__ float g_Wa[(size_t)R4*KA];   // [gate r][k]  (concat Wih_a|Whh_a, row-major)
__device__ float g_Wd[(size_t)R4*KD];   // [gate r][k]  (concat Wih_d|Whh_d, row-major)
__device__ float g_keys[B32*TENC*ATT];
__device__ float g_X[TDEC*B32*PRE];
__device__ float g_zpA[NSPL*B32*R4];
__device__ float g_zpD[NSPL*B32*R4];
__device__ float g_Wqt[HID*ATT];
__device__ float g_Wmt[EDIM*ATT];
__device__ float g_Wp1t[NMELS*PRE];
__device__ float g_Wp2t[PRE*PRE];
__device__ float g_Wldt[LOCF*ATT];
__device__ float g_ba[R4];
__device__ float g_bd[R4];
__device__ float g_cat_a[B32*KA];
__device__ float g_cat_d[B32*KD];
__device__ float g_ac[B32*HID];
__device__ float g_dc[B32*HID];
__device__ float g_aw[B32*TENC];
__device__ float g_awc[B32*TENC];
__device__ float g_q[B32*ATT];
__device__ float g_e[B32*TENC];

// sync state
__device__ unsigned g_barcnt = 0;
__device__ volatile unsigned g_epoch = 0;
__device__ unsigned g_fq = 0;
__device__ unsigned g_fctx = 0;

__device__ __forceinline__ float sigm(float x) { return 1.0f / (1.0f + expf(-x)); }
__device__ __forceinline__ unsigned rotl(unsigned x, int d) { return (x << d) | (x >> (32 - d)); }

__device__ __forceinline__ void gsync() {
    __syncthreads();
    if (threadIdx.x == 0) {
        __threadfence();
        unsigned e = g_epoch;
        if (atomicAdd(&g_barcnt, 1u) == NBLK - 1u) {
            g_barcnt = 0u;
            __threadfence();
            g_epoch = e + 1u;
        } else {
            while (g_epoch == e) { }
        }
        __threadfence();
    }
    __syncthreads();
}

__device__ __forceinline__ void flag_wait(unsigned* flag, unsigned target) {
    if (threadIdx.x == 0) {
        while (*(volatile unsigned*)flag < target) { }
        __threadfence();
    }
    __syncthreads();
}

// TF32 input rounding (same conversion the cuBLAS TF32 path applies)
__device__ __forceinline__ float tf32r(float x) {
    unsigned u;
    asm("cvt.rna.tf32.f32 %0, %1;" : "=r"(u) : "f"(x));
    return __uint_as_float(u);
}

// m16n8k8 row.col f32.tf32.tf32.f32
__device__ __forceinline__ void mma8(float* d, const unsigned* a, unsigned b0, unsigned b1) {
    asm volatile(
        "mma.sync.aligned.m16n8k8.row.col.f32.tf32.tf32.f32 "
        "{%0,%1,%2,%3}, {%4,%5,%6,%7}, {%8,%9}, {%0,%1,%2,%3};"
        : "+f"(d[0]), "+f"(d[1]), "+f"(d[2]), "+f"(d[3])
        : "r"(a[0]), "r"(a[1]), "r"(a[2]), "r"(a[3]), "r"(b0), "r"(b1));
}

// Bit-exact jax.random.bernoulli(jax.random.key(42), 0.5, (512,2,32,256)) * 2.0
// (jax_threefry_partitionable=True)
__device__ float drop_mask(unsigned idx) {
    unsigned x0 = 0u, x1 = idx;
    const unsigned ks0 = 0u, ks1 = 42u, ks2 = 0x1BD11BDAu ^ 42u;
    x0 += ks0; x1 += ks1;
#define RND(r) { x0 += x1; x1 = rotl(x1, r); x1 ^= x0; }
    RND(13) RND(15) RND(26) RND(6)  x0 += ks1; x1 += ks2 + 1u;
    RND(17) RND(29) RND(16) RND(24) x0 += ks2; x1 += ks0 + 2u;
    RND(13) RND(15) RND(26) RND(6)  x0 += ks0; x1 += ks1 + 3u;
    RND(17) RND(29) RND(16) RND(24) x0 += ks1; x1 += ks2 + 4u;
    RND(13) RND(15) RND(26) RND(6)  x0 += ks2; x1 += ks0 + 5u;
#undef RND
    unsigned bits = x0 ^ x1;
    return (bits & 0x80000000u) ? 0.0f : 2.0f;
}

// ---------------- setup helpers (inside k_steps preamble) ----------------
__device__ void keys_unit(const float* __restrict__ memory, int u, float* __restrict__ sh) {
    int b = u & 31, tc = u >> 5;
    int t = threadIdx.x;
    __syncthreads();
    for (int i = t; i < 16 * EDIM; i += 256) {
        int tt = i >> 9, d = i & 511;
        sh[i] = memory[((size_t)(b * TENC + tc * 16 + tt)) * EDIM + d];
    }
    __syncthreads();
    int a = t & 127, r0 = (t >> 7) * 8;
    float acc[8];
#pragma unroll
    for (int j = 0; j < 8; j++) acc[j] = 0.f;
    for (int d4 = 0; d4 < EDIM / 4; d4++) {
        float w0 = g_Wmt[(d4 * 4 + 0) * ATT + a];
        float w1 = g_Wmt[(d4 * 4 + 1) * ATT + a];
        float w2 = g_Wmt[(d4 * 4 + 2) * ATT + a];
        float w3 = g_Wmt[(d4 * 4 + 3) * ATT + a];
#pragma unroll
        for (int tt = 0; tt < 8; tt++) {
            float4 m = *(const float4*)&sh[(r0 + tt) * EDIM + d4 * 4];
            acc[tt] += m.x * w0 + m.y * w1 + m.z * w2 + m.w * w3;
        }
    }
    for (int tt = 0; tt < 8; tt++)
        g_keys[((size_t)(b * TENC + tc * 16 + r0 + tt)) * ATT + a] = acc[tt];
    __syncthreads();
}

__device__ void prenet_unit(const float* __restrict__ mel_target,
                            const float* __restrict__ b_p1,
                            const float* __restrict__ b_p2,
                            int ts, float* __restrict__ sh) {
    int j = threadIdx.x;
    float* sDec = sh;
    float* sX1  = sh + 2560;
    __syncthreads();
    for (int i = j; i < B32 * NMELS; i += 256) {
        int b = i / NMELS, m = i % NMELS;
        sDec[i] = (ts == 0) ? 0.f : mel_target[((size_t)(b * NMELS + m)) * TDEC + (ts - 1)];
    }
    __syncthreads();
    float acc[B32];
#pragma unroll
    for (int b = 0; b < B32; b++) acc[b] = 0.f;
    for (int m4 = 0; m4 < NMELS / 4; m4++) {
        float w0 = g_Wp1t[(4 * m4 + 0) * PRE + j];
        float w1 = g_Wp1t[(4 * m4 + 1) * PRE + j];
        float w2 = g_Wp1t[(4 * m4 + 2) * PRE + j];
        float w3 = g_Wp1t[(4 * m4 + 3) * PRE + j];
#pragma unroll
        for (int b = 0; b < B32; b++) {
            float4 d = *(const float4*)&sDec[b * NMELS + 4 * m4];
            acc[b] += d.x * w0 + d.y * w1 + d.z * w2 + d.w * w3;
        }
    }
    float bb = b_p1[j];
#pragma unroll
    for (int b = 0; b < B32; b++) {
        float v = acc[b] + bb; v = v > 0.f ? v : 0.f;
        v *= drop_mask(((unsigned)(ts * 2 + 0) * B32 + b) * PRE + j);
        sX1[b * PRE + j] = v;
    }
    __syncthreads();
#pragma unroll
    for (int b = 0; b < B32; b++) acc[b] = 0.f;
    for (int k4 = 0; k4 < PRE / 4; k4++) {
        float w0 = g_Wp2t[(4 * k4 + 0) * PRE + j];
        float w1 = g_Wp2t[(4 * k4 + 1) * PRE + j];
        float w2 = g_Wp2t[(4 * k4 + 2) * PRE + j];
        float w3 = g_Wp2t[(4 * k4 + 3) * PRE + j];
#pragma unroll
        for (int b = 0; b < B32; b++) {
            float4 x = *(const float4*)&sX1[b * PRE + 4 * k4];
            acc[b] += x.x * w0 + x.y * w1 + x.z * w2 + x.w * w3;
        }
    }
    bb = b_p2[j];
#pragma unroll
    for (int b = 0; b < B32; b++) {
        float v = acc[b] + bb; v = v > 0.f ? v : 0.f;
        v *= drop_mask(((unsigned)(ts * 2 + 1) * B32 + b) * PRE + j);
        g_X[((size_t)(ts * B32 + b)) * PRE + j] = v;
        if (ts == 0) g_cat_a[b * KA + j] = v;
    }
    __syncthreads();
}

// ---------------- tensor-core GEMM phase ----------------
// D[128 gates x 32 batch] partial over 32-k chunks [c0,c1), acc in registers.
// acc[nt][r]: gate row = mrow0 + warp*16 + lane/4 + (r>=2 ? 8:0),
//             batch   = nt*8 + (lane%4)*2 + (r&1)
template <int K>
__device__ __forceinline__ void gemm_chunks(const float* __restrict__ Wmat,
                                            const float* __restrict__ act,
                                            int mrow0, int c0, int c1,
                                            float (&acc)[4][4],
                                            float* __restrict__ sh) {
    if (c1 <= c0) return;
    int t = threadIdx.x;
    int w = t >> 5, lane = t & 31;
    int rq = t >> 3;          // 0..31 (W row group / act batch)
    int c4 = t & 7;           // 0..7  (k sub-chunk of 4)
    int kb_st = c4 >> 1;      // staging kblock
    // staging destination bases
    float* wdst[4];
#pragma unroll
    for (int p = 0; p < 4; p++) {
        int mrow_t = rq + p * 32;
        int mblock = mrow_t >> 4, mrow = mrow_t & 15;
        int reg = (mrow >> 3) + 2 * (c4 & 1);
        wdst[p] = &sh[((mblock * 4 + kb_st) * 32 + (mrow & 7) * 4) * 4 + reg];
    }
    float* bdst;
    {
        int nt = rq >> 3, reg = c4 & 1;
        bdst = &sh[SH_BFRAG + ((kb_st * 4 + nt) * 32 + (rq & 7) * 4) * 2 + reg];
    }

    float4 rw[4], rb;
    {   // preload chunk c0
        int kc = c0 * 32;
#pragma unroll
        for (int p = 0; p < 4; p++)
            rw[p] = *(const float4*)(Wmat + (size_t)(mrow0 + rq + p * 32) * K + kc + c4 * 4);
        rb = *(const float4*)(act + (size_t)rq * K + kc + c4 * 4);
    }

    for (int c = c0; c < c1; c++) {
        __syncthreads();   // previous compute done reading sh
#pragma unroll
        for (int p = 0; p < 4; p++) {
            wdst[p][0]  = tf32r(rw[p].x);
            wdst[p][4]  = tf32r(rw[p].y);
            wdst[p][8]  = tf32r(rw[p].z);
            wdst[p][12] = tf32r(rw[p].w);
        }
        bdst[0] = tf32r(rb.x);
        bdst[2] = tf32r(rb.y);
        bdst[4] = tf32r(rb.z);
        bdst[6] = tf32r(rb.w);
        __syncthreads();
        if (c + 1 < c1) {   // prefetch next chunk (latency hidden by MMAs)
            int kc = (c + 1) * 32;
#pragma unroll
            for (int p = 0; p < 4; p++)
                rw[p] = *(const float4*)(Wmat + (size_t)(mrow0 + rq + p * 32) * K + kc + c4 * 4);
            rb = *(const float4*)(act + (size_t)rq * K + kc + c4 * 4);
        }
#pragma unroll
        for (int kb = 0; kb < 4; kb++) {
            const unsigned* af = (const unsigned*)&sh[((w * 4 + kb) * 32 + lane) * 4];
            unsigned a[4] = {af[0], af[1], af[2], af[3]};
#pragma unroll
            for (int nt = 0; nt < 4; nt++) {
                const unsigned* bf = (const unsigned*)&sh[SH_BFRAG + ((kb * 4 + nt) * 32 + lane) * 2];
                mma8(acc[nt], a, bf[0], bf[1]);
            }
        }
    }
    __syncthreads();
}

__device__ __forceinline__ void zp_store(float* __restrict__ zp, float (&acc)[4][4],
                                         int s, int mrow0) {
    int t = threadIdx.x, w = t >> 5, lane = t & 31;
    int g0 = mrow0 + w * 16 + (lane >> 2);
    int b0 = (lane & 3) * 2;
#pragma unroll
    for (int nt = 0; nt < 4; nt++)
#pragma unroll
        for (int r = 0; r < 4; r++) {
            int gate = g0 + ((r >= 2) ? 8 : 0);
            int bb = nt * 8 + b0 + (r & 1);
            zp[(size_t)(s * B32 + bb) * R4 + gate] = acc[nt][r];
        }
}

// ---------------- other phase bodies ----------------
__device__ __forceinline__ void combineA_phase(int b, float* __restrict__ sh) {
    int t = threadIdx.x;
    float* sAh = sh;
    float* sQ = sh + 1024;
#pragma unroll
    for (int u = 0; u < 4; u++) {
        int h = u * 256 + t;
        float zi = g_ba[h], zf = g_ba[HID + h], zg = g_ba[2 * HID + h], zo = g_ba[3 * HID + h];
#pragma unroll
        for (int sp = 0; sp < NSPL; sp++) {
            const float* zp = &g_zpA[((size_t)(sp * B32 + b)) * R4];
            zi += zp[h]; zf += zp[HID + h]; zg += zp[2 * HID + h]; zo += zp[3 * HID + h];
        }
        float c = sigm(zf) * g_ac[b * HID + h] + sigm(zi) * tanhf(zg);
        float hn = sigm(zo) * tanhf(c);
        g_ac[b * HID + h] = c;
        sAh[h] = hn;
        g_cat_a[b * KA + 768 + h] = hn;
        g_cat_d[b * KD + h] = hn;
    }
    __syncthreads();
    int a = t & 127, half = t >> 7;
    int j0 = half * 512;
    float a0 = 0.f, a1 = 0.f, a2 = 0.f, a3 = 0.f;
    for (int j = 0; j < 512; j += 4) {
        a0 += sAh[j0 + j]     * g_Wqt[(j0 + j) * ATT + a];
        a1 += sAh[j0 + j + 1] * g_Wqt[(j0 + j + 1) * ATT + a];
        a2 += sAh[j0 + j + 2] * g_Wqt[(j0 + j + 2) * ATT + a];
        a3 += sAh[j0 + j + 3] * g_Wqt[(j0 + j + 3) * ATT + a];
    }
    sQ[half * ATT + a] = (a0 + a1) + (a2 + a3);
    __syncthreads();
    if (t < ATT) g_q[b * ATT + t] = sQ[t] + sQ[ATT + t];
    __syncthreads();
    if (t == 0) { __threadfence(); atomicAdd(&g_fq, 1u); }
}

__device__ __forceinline__ void att1_phase(const float* __restrict__ W_loc,
                                           const float* __restrict__ b_loc,
                                           const float* __restrict__ Wv,
                                           const int* __restrict__ mem_len,
                                           unsigned fq_target,
                                           float* __restrict__ sh) {
    int bx = blockIdx.x;
    int b = bx & 31, tc = bx >> 5;
    int t = threadIdx.x;
    int tbase = tc * 64;
    float* sAw0 = sh;
    float* sAw1 = sh + 96;
    float* sQ   = sh + 192;
    float* sWl  = sh + 320;
    float* sLoc = sh + 2304;
    float* sEp  = sh + 4352;
    for (int i = t; i < 94; i += 256) {
        int tt = tbase - 15 + i;
        bool ok = (tt >= 0) && (tt < TENC);
        sAw0[i] = ok ? g_aw[b * TENC + tt] : 0.f;
        sAw1[i] = ok ? g_awc[b * TENC + tt] : 0.f;
    }
    for (int i = t; i < LOCF * 2 * LOCK; i += 256) sWl[i] = W_loc[i];
    __syncthreads();
    for (int i = t; i < 64 * LOCF; i += 256) {
        int f = i & 31, tt = i >> 5;
        const float* w0 = &sWl[f * 62];
        const float* w1 = &sWl[f * 62 + 31];
        float c0 = b_loc[f], c1 = 0.f, c2 = 0.f, c3 = 0.f;
#pragma unroll
        for (int k = 0; k < 30; k += 2) {
            c0 += sAw0[tt + k] * w0[k];
            c1 += sAw0[tt + k + 1] * w0[k + 1];
            c2 += sAw1[tt + k] * w1[k];
            c3 += sAw1[tt + k + 1] * w1[k + 1];
        }
        c0 += sAw0[tt + 30] * w0[30];
        c2 += sAw1[tt + 30] * w1[30];
        sLoc[tt * 32 + f] = (c0 + c1) + (c2 + c3);
    }
    flag_wait(&g_fq, fq_target);
    if (t < ATT) sQ[t] = g_q[b * ATT + t];
    __syncthreads();
    int a = t & 127;
    int half = t >> 7;
    float wld[32];
#pragma unroll
    for (int f = 0; f < 32; f++) wld[f] = g_Wldt[f * ATT + a];
    float wv = Wv[a];
    float qa = sQ[a];
    int lane = t & 31, w = t >> 5;
#pragma unroll 2
    for (int tl = 0; tl < 32; tl++) {
        int tt = half * 32 + tl;
        float l0 = 0.f, l1 = 0.f, l2 = 0.f, l3 = 0.f;
#pragma unroll
        for (int f = 0; f < 8; f++) {
            l0 += sLoc[tt * 32 + f]      * wld[f];
            l1 += sLoc[tt * 32 + f + 8]  * wld[f + 8];
            l2 += sLoc[tt * 32 + f + 16] * wld[f + 16];
            l3 += sLoc[tt * 32 + f + 24] * wld[f + 24];
        }
        float lA = (l0 + l1) + (l2 + l3);
        float v = tanhf(qa + g_keys[((size_t)(b * TENC + tbase + tt)) * ATT + a] + lA) * wv;
        for (int off = 16; off; off >>= 1) v += __shfl_down_sync(0xffffffffu, v, off);
        if (lane == 0) sEp[w * 32 + tl] = v;
    }
    __syncthreads();
    int L = mem_len[b];
    for (int tt = t; tt < 64; tt += 256) {
        float e;
        if (tt < 32) e = sEp[tt] + sEp[32 + tt] + sEp[64 + tt] + sEp[96 + tt];
        else { int tl = tt - 32; e = sEp[128 + tl] + sEp[160 + tl] + sEp[192 + tl] + sEp[224 + tl]; }
        int tg = tbase + tt;
        g_e[b * TENC + tg] = (tg >= L) ? -1e30f : e;
    }
}

__device__ __forceinline__ void att2_phase(const float* __restrict__ memory, int b,
                                           float* __restrict__ dout, int tstep,
                                           float* __restrict__ sh) {
    int t = threadIdx.x;
    float* sE = sh;
    float* sR1 = sh + 256;
    float* sR2 = sh + 264;
    sE[t] = g_e[b * TENC + t];
    __syncthreads();
    float v = sE[t];
    for (int off = 16; off; off >>= 1) v = fmaxf(v, __shfl_down_sync(0xffffffffu, v, off));
    if ((t & 31) == 0) sR1[t >> 5] = v;
    __syncthreads();
    if (t < 8) {
        float m = sR1[t];
        for (int off = 4; off; off >>= 1) m = fmaxf(m, __shfl_down_sync(0xffu, m, off));
        if (t == 0) sR1[0] = m;
    }
    __syncthreads();
    float mx = sR1[0];
    float p = expf(sE[t] - mx);
    float sv = p;
    for (int off = 16; off; off >>= 1) sv += __shfl_down_sync(0xffffffffu, sv, off);
    if ((t & 31) == 0) sR2[t >> 5] = sv;
    __syncthreads();
    if (t < 8) {
        float m = sR2[t];
        for (int off = 4; off; off >>= 1) m += __shfl_down_sync(0xffu, m, off);
        if (t == 0) sR2[0] = m;
    }
    __syncthreads();
    float aw = p / sR2[0];
    __syncthreads();
    sE[t] = aw;
    g_aw[b * TENC + t] = aw;
    g_awc[b * TENC + t] += aw;
    dout[ALIGN_OFF + ((size_t)(b * TDEC + tstep)) * TENC + t] = aw;
    __syncthreads();
    int d = t;
    float p00 = 0.f, p01 = 0.f, p02 = 0.f, p03 = 0.f;
    float p10 = 0.f, p11 = 0.f, p12 = 0.f, p13 = 0.f;
    for (int tt = 0; tt < TENC; tt += 4) {
        const float* m0 = &memory[((size_t)(b * TENC + tt)) * EDIM];
        float a0 = sE[tt], a1 = sE[tt + 1], a2 = sE[tt + 2], a3 = sE[tt + 3];
        p00 += a0 * m0[d];               p10 += a0 * m0[d + 256];
        p01 += a1 * m0[EDIM + d];        p11 += a1 * m0[EDIM + d + 256];
        p02 += a2 * m0[2 * EDIM + d];    p12 += a2 * m0[2 * EDIM + d + 256];
        p03 += a3 * m0[3 * EDIM + d];    p13 += a3 * m0[3 * EDIM + d + 256];
    }
    float acc0 = (p00 + p01) + (p02 + p03);
    float acc1 = (p10 + p11) + (p12 + p13);
    g_cat_a[b * KA + 256 + d] = acc0;
    g_cat_a[b * KA + 256 + d + 256] = acc1;
    g_cat_d[b * KD + HID + d] = acc0;
    g_cat_d[b * KD + HID + d + 256] = acc1;
    __syncthreads();
    if (t == 0) { __threadfence(); atomicAdd(&g_fctx, 1u); }
    __syncthreads();
}

__device__ __forceinline__ void combineD_phase(int b,
                                               const float* __restrict__ W_lin,
                                               const float* __restrict__ b_lin,
                                               const float* __restrict__ W_gate,
                                               const float* __restrict__ b_gate,
                                               float* __restrict__ dout, int tstep,
                                               float* __restrict__ sh) {
    int t = threadIdx.x;
    float* sOut = sh;
#pragma unroll
    for (int u = 0; u < 4; u++) {
        int h = u * 256 + t;
        float zi = g_bd[h], zf = g_bd[HID + h], zg = g_bd[2 * HID + h], zo = g_bd[3 * HID + h];
#pragma unroll
        for (int sp = 0; sp < NSPL; sp++) {
            const float* zp = &g_zpD[((size_t)(sp * B32 + b)) * R4];
            zi += zp[h]; zf += zp[HID + h]; zg += zp[2 * HID + h]; zo += zp[3 * HID + h];
        }
        float c = sigm(zf) * g_dc[b * HID + h] + sigm(zi) * tanhf(zg);
        float hn = sigm(zo) * tanhf(c);
        g_dc[b * HID + h] = c;
        g_cat_d[b * KD + 1536 + h] = hn;
        sOut[h] = hn;
    }
    for (int i = t; i < EDIM; i += 256) sOut[HID + i] = g_cat_d[b * KD + HID + i];
    __syncthreads();
    int lane = t & 31, w = t >> 5;
    for (int m = w; m < 81; m += 8) {
        const float* row; float bias;
        if (m < 80) { row = W_lin + (size_t)m * 1536; bias = b_lin[m]; }
        else        { row = W_gate; bias = b_gate[0]; }
        float a0 = 0.f, a1 = 0.f, a2 = 0.f, a3 = 0.f;
        for (int k = lane; k < 1536; k += 128) {
            a0 += sOut[k] * row[k];
            a1 += sOut[k + 32] * row[k + 32];
            a2 += sOut[k + 64] * row[k + 64];
            a3 += sOut[k + 96] * row[k + 96];
        }
        float acc = (a0 + a1) + (a2 + a3);
        for (int off = 16; off; off >>= 1) acc += __shfl_down_sync(0xffffffffu, acc, off);
        if (lane == 0) {
            float r = acc + bias;
            if (m < 80) dout[((size_t)(b * NMELS + m)) * TDEC + tstep] = r;
            else        dout[GATE_OFF + b * TDEC + tstep] = r;
        }
    }
}

__device__ __forceinline__ void xcopy_phase(int b, int tstep) {
    int t = threadIdx.x;
    g_cat_a[b * KA + t] = g_X[((size_t)(tstep * B32 + b)) * PRE + t];
}

// ---------------- the single persistent kernel ----------------
__global__ void __launch_bounds__(NTHR) k_steps(
    const float* __restrict__ memory, const float* __restrict__ mel_target,
    const int* __restrict__ mem_len,
    const float* __restrict__ W_p1, const float* __restrict__ b_p1,
    const float* __restrict__ W_p2, const float* __restrict__ b_p2,
    const float* __restrict__ Wih_a, const float* __restrict__ Whh_a,
    const float* __restrict__ bih_a, const float* __restrict__ bhh_a,
    const float* __restrict__ Wq, const float* __restrict__ Wm,
    const float* __restrict__ Wv, const float* __restrict__ W_loc,
    const float* __restrict__ b_loc, const float* __restrict__ W_locd,
    const float* __restrict__ Wih_d, const float* __restrict__ Whh_d,
    const float* __restrict__ bih_d, const float* __restrict__ bhh_d,
    const float* __restrict__ W_lin, const float* __restrict__ b_lin,
    const float* __restrict__ W_gate, const float* __restrict__ b_gate,
    float* __restrict__ dout) {
    __shared__ __align__(16) float sh[10752];
    int bx = blockIdx.x;
    int tid = threadIdx.x;

    // ---- setup S1: state init + small transposes + weight concat (grid-strided) ----
    {
        int gtid = bx * NTHR + tid;
        const int GN = NBLK * NTHR;
        for (int i = gtid; i < B32*KA;   i += GN) g_cat_a[i] = 0.f;
        for (int i = gtid; i < B32*KD;   i += GN) g_cat_d[i] = 0.f;
        for (int i = gtid; i < B32*HID;  i += GN) { g_ac[i] = 0.f; g_dc[i] = 0.f; }
        for (int i = gtid; i < B32*TENC; i += GN) { g_aw[i] = 0.f; g_awc[i] = 0.f; }
        for (int i = gtid; i < R4;       i += GN) { g_ba[i] = bih_a[i] + bhh_a[i]; g_bd[i] = bih_d[i] + bhh_d[i]; }
        for (int i = gtid; i < HID*ATT;  i += GN) { int k = i >> 7, a = i & 127; g_Wqt[i]  = Wq[a*HID + k]; }
        for (int i = gtid; i < EDIM*ATT; i += GN) { int k = i >> 7, a = i & 127; g_Wmt[i]  = Wm[a*EDIM + k]; }
        for (int i = gtid; i < NMELS*PRE;i += GN) { int m = i >> 8, j = i & 255; g_Wp1t[i] = W_p1[j*NMELS + m]; }
        for (int i = gtid; i < PRE*PRE;  i += GN) { int k = i >> 8, j = i & 255; g_Wp2t[i] = W_p2[j*PRE + k]; }
        for (int i = gtid; i < LOCF*ATT; i += GN) { int f = i >> 7, a = i & 127; g_Wldt[i] = W_locd[a*LOCF + f]; }
        if (gtid == 0) { g_fq = 0u; g_fctx = 0u; }
        // weight concatenation (row-major, K-contiguous)
        for (int r = bx; r < R4; r += NBLK) {
            const float* s1 = Wih_a + (size_t)r * 768;
            const float* s2 = Whh_a + (size_t)r * 1024;
            float* dst = g_Wa + (size_t)r * KA;
            for (int k = tid; k < 768; k += NTHR) dst[k] = s1[k];
            for (int k = tid; k < 1024; k += NTHR) dst[768 + k] = s2[k];
        }
        for (int r = bx; r < R4; r += NBLK) {
            const float* s1 = Wih_d + (size_t)r * 1536;
            const float* s2 = Whh_d + (size_t)r * 1024;
            float* dst = g_Wd + (size_t)r * KD;
            for (int k = tid; k < 1536; k += NTHR) dst[k] = s1[k];
            for (int k = tid; k < 1024; k += NTHR) dst[1536 + k] = s2[k];
        }
    }
    gsync();
    // ---- setup S2: keys + prenet ----
    for (int u = bx; u < 512; u += NBLK) keys_unit(memory, u, sh);
    for (int ts = bx; ts < TDEC; ts += NBLK) prenet_unit(mel_target, b_p1, b_p2, ts, sh);
    gsync();

    // ---- main loop ----
    int mtile = bx & 31, s = bx >> 5;
    int mrow0 = mtile * 128;
    // GEMM-D chunk tables (32-k chunks; ctx = chunks [32,48))
    const int dA0s[4] = {0, 16, 48, 64};
    const int dA1s[4] = {16, 32, 64, 80};
    const int dB0s[4] = {0, 32, 37, 42};
    const int dB1s[4] = {0, 37, 42, 48};
    int dA0 = dA0s[s], dA1 = dA1s[s], dB0 = dB0s[s], dB1 = dB1s[s];

    for (int tstep = 0; tstep < TDEC; tstep++) {
        unsigned ftarget = 32u * (unsigned)(tstep + 1);

        // P_G1: attention-LSTM gate GEMM (tensor cores, 4 K-splits of 14 chunks)
        {
            float acc[4][4];
#pragma unroll
            for (int i = 0; i < 4; i++)
#pragma unroll
                for (int j = 0; j < 4; j++) acc[i][j] = 0.f;
            gemm_chunks<KA>(g_Wa, g_cat_a, mrow0, s * 14, s * 14 + 14, acc, sh);
            zp_store(g_zpA, acc, s, mrow0);
        }
        gsync();

        // P_MID
        if (bx < 32)       combineA_phase(bx, sh);
        else if (bx < 64)  { if (tstep > 0) combineD_phase(bx - 32, W_lin, b_lin, W_gate, b_gate, dout, tstep - 1, sh); }
        else if (bx < 96)  { if (tstep + 1 < TDEC) xcopy_phase(bx - 64, tstep + 1); }
        __syncthreads();
        att1_phase(W_loc, b_loc, Wv, mem_len, ftarget, sh);
        gsync();

        // P_G2: att2 (blocks 0-31) + decoder gate GEMM (ctx chunks gated on fctx)
        {
            if (s == 0) att2_phase(memory, bx, dout, tstep, sh);
            float acc[4][4];
#pragma unroll
            for (int i = 0; i < 4; i++)
#pragma unroll
                for (int j = 0; j < 4; j++) acc[i][j] = 0.f;
            gemm_chunks<KD>(g_Wd, g_cat_d, mrow0, dA0, dA1, acc, sh);
            if (dB1 > dB0) {
                flag_wait(&g_fctx, ftarget);
                gemm_chunks<KD>(g_Wd, g_cat_d, mrow0, dB0, dB1, acc, sh);
            }
            zp_store(g_zpD, acc, s, mrow0);
        }
        gsync();
    }
    if (bx >= 32 && bx < 64)
        combineD_phase(bx - 32, W_lin, b_lin, W_gate, b_gate, dout, TDEC - 1, sh);
}

// ---------------- host ----------------
extern "C" void kernel_launch(void* const* d_in, const int* in_sizes, int n_in,
                              void* d_out, int out_size) {
    const float* memory   = (const float*)d_in[0];
    const float* mel_tgt  = (const float*)d_in[1];
    const int*   mem_len  = (const int*)  d_in[2];
    const float* W_p1     = (const float*)d_in[3];
    const float* b_p1     = (const float*)d_in[4];
    const float* W_p2     = (const float*)d_in[5];
    const float* b_p2     = (const float*)d_in[6];
    const float* Wih_a    = (const float*)d_in[7];
    const float* Whh_a    = (const float*)d_in[8];
    const float* bih_a    = (const float*)d_in[9];
    const float* bhh_a    = (const float*)d_in[10];
    const float* Wq       = (const float*)d_in[11];
    const float* Wm       = (const float*)d_in[12];
    const float* Wv       = (const float*)d_in[13];
    const float* W_loc    = (const float*)d_in[14];
    const float* b_loc    = (const float*)d_in[15];
    const float* W_locd   = (const float*)d_in[16];
    const float* Wih_d    = (const float*)d_in[17];
    const float* Whh_d    = (const float*)d_in[18];
    const float* bih_d    = (const float*)d_in[19];
    const float* bhh_d    = (const float*)d_in[20];
    const float* W_lin    = (const float*)d_in[21];
    const float* b_lin    = (const float*)d_in[22];
    const float* W_gate   = (const float*)d_in[23];
    const float* b_gate   = (const float*)d_in[24];
    float* out = (float*)d_out;

    k_steps<<<NBLK, NTHR>>>(memory, mel_tgt, mem_len,
                            W_p1, b_p1, W_p2, b_p2,
                            Wih_a, Whh_a, bih_a, bhh_a,
                            Wq, Wm, Wv, W_loc, b_loc, W_locd,
                            Wih_d, Whh_d, bih_d, bhh_d,
                            W_lin, b_lin, W_gate, b_gate, out);
}

// round 17
// speedup vs baseline: 1.0376x; 1.0376x over previous
#include <cuda_runtime.h>
#include <math.h>
#include <stdint.h>

// ---------------- problem constants ----------------
#define B32    32
#define TENC   256
#define TDEC   512
#define NMELS  80
#define EDIM   512
#define PRE    256
#define HID    1024
#define ATT    128
#define LOCF   32
#define LOCK   31
#define KA     1792           // PRE + EDIM + HID  (x | ctx | ah)
#define KD     2560           // HID + EDIM + HID  (ah | ctx | dh)
#define R4     4096
#define NSPL   4
#define NBLK   128
#define NTHR   512

#define MEL_SZ    (B32*NMELS*TDEC)
#define GATE_OFF  MEL_SZ
#define ALIGN_OFF (MEL_SZ + B32*TDEC)

#define SH_BFRAG 4096   // B-frags after A-frags

// ---------------- static device buffers ----------------
__device__ float g_Wa[(size_t)R4*KA];   // [gate r][k]
__device__ float g_Wd[(size_t)R4*KD];   // [gate r][k]
__device__ float g_keys[B32*TENC*ATT];
__device__ float g_X[TDEC*B32*PRE];
__device__ float g_zpA[NSPL*B32*R4];
__device__ float g_zpD[NSPL*B32*R4];
__device__ float g_Wqt[HID*ATT];
__device__ float g_Wmt[EDIM*ATT];
__device__ float g_Wp1t[NMELS*PRE];
__device__ float g_Wp2t[PRE*PRE];
__device__ float g_Wldt[LOCF*ATT];
__device__ float g_ba[R4];
__device__ float g_bd[R4];
__device__ float g_cat_a[B32*KA];
__device__ float g_cat_d[B32*KD];
__device__ float g_ac[B32*HID];
__device__ float g_dc[B32*HID];
__device__ float g_aw[B32*TENC];
__device__ float g_awc[B32*TENC];
__device__ float g_q[B32*ATT];
__device__ float g_e[B32*TENC];

// sync state (all reset each replay in setup S1)
__device__ unsigned g_barcnt = 0;
__device__ volatile unsigned g_epoch = 0;
__device__ unsigned g_fq = 0;      // combineA done (32/step)
__device__ unsigned g_fctx = 0;    // att2 done (32/step)
__device__ unsigned g_fgA = 0;     // GEMM-A done (128/step)
__device__ unsigned g_fdh = 0;     // combineD done (32/step, from step 1)
__device__ unsigned g_fe[B32];     // att1 chunks done per batch (4/step)

__device__ __forceinline__ float sigm(float x) { return 1.0f / (1.0f + expf(-x)); }
__device__ __forceinline__ unsigned rotl(unsigned x, int d) { return (x << d) | (x >> (32 - d)); }

__device__ __forceinline__ void gsync() {
    __syncthreads();
    if (threadIdx.x == 0) {
        __threadfence();
        unsigned e = g_epoch;
        if (atomicAdd(&g_barcnt, 1u) == NBLK - 1u) {
            g_barcnt = 0u;
            __threadfence();
            g_epoch = e + 1u;
        } else {
            while (g_epoch == e) { }
        }
        __threadfence();
    }
    __syncthreads();
}

__device__ __forceinline__ void flag_wait(unsigned* flag, unsigned target) {
    if (threadIdx.x == 0) {
        while (*(volatile unsigned*)flag < target) { }
        __threadfence();
    }
    __syncthreads();
}

// block-wide release: all threads' prior writes, then count
__device__ __forceinline__ void flag_add(unsigned* flag) {
    __syncthreads();
    if (threadIdx.x == 0) { __threadfence(); atomicAdd(flag, 1u); }
}

// TF32 input rounding (cuBLAS-style)
__device__ __forceinline__ float tf32r(float x) {
    unsigned u;
    asm("cvt.rna.tf32.f32 %0, %1;" : "=r"(u) : "f"(x));
    return __uint_as_float(u);
}

// m16n8k8 row.col f32.tf32.tf32.f32
__device__ __forceinline__ void mma8(float* d, const unsigned* a, unsigned b0, unsigned b1) {
    asm volatile(
        "mma.sync.aligned.m16n8k8.row.col.f32.tf32.tf32.f32 "
        "{%0,%1,%2,%3}, {%4,%5,%6,%7}, {%8,%9}, {%0,%1,%2,%3};"
        : "+f"(d[0]), "+f"(d[1]), "+f"(d[2]), "+f"(d[3])
        : "r"(a[0]), "r"(a[1]), "r"(a[2]), "r"(a[3]), "r"(b0), "r"(b1));
}

// Bit-exact jax.random.bernoulli(jax.random.key(42), 0.5, (512,2,32,256)) * 2.0
// (jax_threefry_partitionable=True)
__device__ float drop_mask(unsigned idx) {
    unsigned x0 = 0u, x1 = idx;
    const unsigned ks0 = 0u, ks1 = 42u, ks2 = 0x1BD11BDAu ^ 42u;
    x0 += ks0; x1 += ks1;
#define RND(r) { x0 += x1; x1 = rotl(x1, r); x1 ^= x0; }
    RND(13) RND(15) RND(26) RND(6)  x0 += ks1; x1 += ks2 + 1u;
    RND(17) RND(29) RND(16) RND(24) x0 += ks2; x1 += ks0 + 2u;
    RND(13) RND(15) RND(26) RND(6)  x0 += ks0; x1 += ks1 + 3u;
    RND(17) RND(29) RND(16) RND(24) x0 += ks1; x1 += ks2 + 4u;
    RND(13) RND(15) RND(26) RND(6)  x0 += ks2; x1 += ks0 + 5u;
#undef RND
    unsigned bits = x0 ^ x1;
    return (bits & 0x80000000u) ? 0.0f : 2.0f;
}

// ---------------- setup helpers ----------------
__device__ void keys_unit(const float* __restrict__ memory, int u, float* __restrict__ sh) {
    int b = u & 31, tc = u >> 5;
    int t = threadIdx.x;
    __syncthreads();
    for (int i = t; i < 16 * EDIM; i += NTHR) {
        int tt = i >> 9, d = i & 511;
        sh[i] = memory[((size_t)(b * TENC + tc * 16 + tt)) * EDIM + d];
    }
    __syncthreads();
    int a = t & 127, r0 = (t >> 7) * 4;
    float acc[4];
#pragma unroll
    for (int j = 0; j < 4; j++) acc[j] = 0.f;
    for (int d4 = 0; d4 < EDIM / 4; d4++) {
        float w0 = g_Wmt[(d4 * 4 + 0) * ATT + a];
        float w1 = g_Wmt[(d4 * 4 + 1) * ATT + a];
        float w2 = g_Wmt[(d4 * 4 + 2) * ATT + a];
        float w3 = g_Wmt[(d4 * 4 + 3) * ATT + a];
#pragma unroll
        for (int tt = 0; tt < 4; tt++) {
            float4 m = *(const float4*)&sh[(r0 + tt) * EDIM + d4 * 4];
            acc[tt] += m.x * w0 + m.y * w1 + m.z * w2 + m.w * w3;
        }
    }
    for (int tt = 0; tt < 4; tt++)
        g_keys[((size_t)(b * TENC + tc * 16 + r0 + tt)) * ATT + a] = acc[tt];
    __syncthreads();
}

__device__ void prenet_unit(const float* __restrict__ mel_target,
                            const float* __restrict__ b_p1,
                            const float* __restrict__ b_p2,
                            int ts, float* __restrict__ sh) {
    int t = threadIdx.x;
    int j = t & 255, bh = t >> 8;       // bh 0/1 -> batches bh*16..bh*16+15
    int bb0 = bh * 16;
    float* sDec = sh;
    float* sX1  = sh + 2560;
    __syncthreads();
    for (int i = t; i < B32 * NMELS; i += NTHR) {
        int b = i / NMELS, m = i % NMELS;
        sDec[i] = (ts == 0) ? 0.f : mel_target[((size_t)(b * NMELS + m)) * TDEC + (ts - 1)];
    }
    __syncthreads();
    float acc[16];
#pragma unroll
    for (int bi = 0; bi < 16; bi++) acc[bi] = 0.f;
    for (int m4 = 0; m4 < NMELS / 4; m4++) {
        float w0 = g_Wp1t[(4 * m4 + 0) * PRE + j];
        float w1 = g_Wp1t[(4 * m4 + 1) * PRE + j];
        float w2 = g_Wp1t[(4 * m4 + 2) * PRE + j];
        float w3 = g_Wp1t[(4 * m4 + 3) * PRE + j];
#pragma unroll
        for (int bi = 0; bi < 16; bi++) {
            float4 d = *(const float4*)&sDec[(bb0 + bi) * NMELS + 4 * m4];
            acc[bi] += d.x * w0 + d.y * w1 + d.z * w2 + d.w * w3;
        }
    }
    float bb = b_p1[j];
#pragma unroll
    for (int bi = 0; bi < 16; bi++) {
        int b = bb0 + bi;
        float v = acc[bi] + bb; v = v > 0.f ? v : 0.f;
        v *= drop_mask(((unsigned)(ts * 2 + 0) * B32 + b) * PRE + j);
        sX1[b * PRE + j] = v;
    }
    __syncthreads();
#pragma unroll
    for (int bi = 0; bi < 16; bi++) acc[bi] = 0.f;
    for (int k4 = 0; k4 < PRE / 4; k4++) {
        float w0 = g_Wp2t[(4 * k4 + 0) * PRE + j];
        float w1 = g_Wp2t[(4 * k4 + 1) * PRE + j];
        float w2 = g_Wp2t[(4 * k4 + 2) * PRE + j];
        float w3 = g_Wp2t[(4 * k4 + 3) * PRE + j];
#pragma unroll
        for (int bi = 0; bi < 16; bi++) {
            float4 x = *(const float4*)&sX1[(bb0 + bi) * PRE + 4 * k4];
            acc[bi] += x.x * w0 + x.y * w1 + x.z * w2 + x.w * w3;
        }
    }
    bb = b_p2[j];
#pragma unroll
    for (int bi = 0; bi < 16; bi++) {
        int b = bb0 + bi;
        float v = acc[bi] + bb; v = v > 0.f ? v : 0.f;
        v *= drop_mask(((unsigned)(ts * 2 + 1) * B32 + b) * PRE + j);
        g_X[((size_t)(ts * B32 + b)) * PRE + j] = v;
        if (ts == 0) g_cat_a[b * KA + j] = v;
    }
    __syncthreads();
}

// ---------------- tensor-core GEMM (512 threads, warp-paired k-split) ----------------
// D[128 gates x 32 batch] over 32-k chunks [c0,c1). Warp w: mblock=w&7, kb in {2*(w>>3), +1}.
template <int K>
__device__ __forceinline__ void gemm_chunks(const float* __restrict__ Wmat,
                                            const float* __restrict__ act,
                                            int mrow0, int c0, int c1,
                                            float (&acc)[4][4],
                                            float* __restrict__ sh) {
    if (c1 <= c0) return;
    int t = threadIdx.x;
    int w = t >> 5, lane = t & 31;
    int rowt = t >> 3;        // 0..63
    int c4 = t & 7;
    int kb_st = c4 >> 1;
    float* wdst[2];
#pragma unroll
    for (int p = 0; p < 2; p++) {
        int row = rowt + p * 64;
        int mblock = row >> 4, mrow = row & 15;
        int reg = (mrow >> 3) + 2 * (c4 & 1);
        wdst[p] = &sh[((mblock * 4 + kb_st) * 32 + (mrow & 7) * 4) * 4 + reg];
    }
    float* bdst = 0;
    if (t < 256) {
        int brow = t >> 3;
        int nt = brow >> 3, reg = c4 & 1;
        bdst = &sh[SH_BFRAG + ((kb_st * 4 + nt) * 32 + (brow & 7) * 4) * 2 + reg];
    }
    int w2 = w & 7, kb0 = (w >> 3) * 2;

    float4 rw[2], rb;
    {
        int kc = c0 * 32;
#pragma unroll
        for (int p = 0; p < 2; p++)
            rw[p] = *(const float4*)(Wmat + (size_t)(mrow0 + rowt + p * 64) * K + kc + c4 * 4);
        if (t < 256) rb = *(const float4*)(act + (size_t)(t >> 3) * K + kc + c4 * 4);
    }
    for (int c = c0; c < c1; c++) {
        __syncthreads();
#pragma unroll
        for (int p = 0; p < 2; p++) {
            wdst[p][0]  = tf32r(rw[p].x);
            wdst[p][4]  = tf32r(rw[p].y);
            wdst[p][8]  = tf32r(rw[p].z);
            wdst[p][12] = tf32r(rw[p].w);
        }
        if (t < 256) {
            bdst[0] = tf32r(rb.x);
            bdst[2] = tf32r(rb.y);
            bdst[4] = tf32r(rb.z);
            bdst[6] = tf32r(rb.w);
        }
        __syncthreads();
        if (c + 1 < c1) {
            int kc = (c + 1) * 32;
#pragma unroll
            for (int p = 0; p < 2; p++)
                rw[p] = *(const float4*)(Wmat + (size_t)(mrow0 + rowt + p * 64) * K + kc + c4 * 4);
            if (t < 256) rb = *(const float4*)(act + (size_t)(t >> 3) * K + kc + c4 * 4);
        }
#pragma unroll
        for (int kb = 0; kb < 2; kb++) {
            int kbi = kb0 + kb;
            const unsigned* af = (const unsigned*)&sh[((w2 * 4 + kbi) * 32 + lane) * 4];
            unsigned a[4] = {af[0], af[1], af[2], af[3]};
#pragma unroll
            for (int nt = 0; nt < 4; nt++) {
                const unsigned* bf = (const unsigned*)&sh[SH_BFRAG + ((kbi * 4 + nt) * 32 + lane) * 2];
                mma8(acc[nt], a, bf[0], bf[1]);
            }
        }
    }
    __syncthreads();
}

// reduce warp pairs through smem (padded [batch][row]) + coalesced store
__device__ __forceinline__ void zp_store(float* __restrict__ zp, float (&acc)[4][4],
                                         int s, int mrow0, float* __restrict__ sh) {
    int t = threadIdx.x, w = t >> 5, lane = t & 31, w2 = w & 7;
    int rowb = w2 * 16 + (lane >> 2), colb = (lane & 3) * 2;
    if (w < 8) {
#pragma unroll
        for (int nt = 0; nt < 4; nt++)
#pragma unroll
            for (int r = 0; r < 4; r++)
                sh[(nt * 8 + colb + (r & 1)) * 132 + rowb + ((r >= 2) ? 8 : 0)] = acc[nt][r];
    }
    __syncthreads();
    if (w >= 8) {
#pragma unroll
        for (int nt = 0; nt < 4; nt++)
#pragma unroll
            for (int r = 0; r < 4; r++)
                sh[(nt * 8 + colb + (r & 1)) * 132 + rowb + ((r >= 2) ? 8 : 0)] += acc[nt][r];
    }
    __syncthreads();
    int b = t >> 4, r0 = (t & 15) * 8;
    float* dst = &zp[(size_t)(s * B32 + b) * R4 + mrow0 + r0];
    const float* src = &sh[b * 132 + r0];
#pragma unroll
    for (int i = 0; i < 8; i++) dst[i] = src[i];
    __syncthreads();
}

// ---------------- per-step phases ----------------
__device__ __forceinline__ void combineA_phase(int b, float* __restrict__ sh) {
    int t = threadIdx.x;
    float* sAh = sh;          // [1024]
    float* sQ = sh + 1024;    // [4][128]
#pragma unroll
    for (int u = 0; u < 2; u++) {
        int h = u * 512 + t;
        float zi = g_ba[h], zf = g_ba[HID + h], zg = g_ba[2 * HID + h], zo = g_ba[3 * HID + h];
#pragma unroll
        for (int sp = 0; sp < NSPL; sp++) {
            const float* zp = &g_zpA[((size_t)(sp * B32 + b)) * R4];
            zi += zp[h]; zf += zp[HID + h]; zg += zp[2 * HID + h]; zo += zp[3 * HID + h];
        }
        float c = sigm(zf) * g_ac[b * HID + h] + sigm(zi) * tanhf(zg);
        float hn = sigm(zo) * tanhf(c);
        g_ac[b * HID + h] = c;
        sAh[h] = hn;
        g_cat_a[b * KA + 768 + h] = hn;
        g_cat_d[b * KD + h] = hn;
    }
    __syncthreads();
    int a = t & 127, q4 = t >> 7;
    int j0 = q4 * 256;
    float a0 = 0.f, a1 = 0.f, a2 = 0.f, a3 = 0.f;
    for (int j = 0; j < 256; j += 4) {
        a0 += sAh[j0 + j]     * g_Wqt[(j0 + j) * ATT + a];
        a1 += sAh[j0 + j + 1] * g_Wqt[(j0 + j + 1) * ATT + a];
        a2 += sAh[j0 + j + 2] * g_Wqt[(j0 + j + 2) * ATT + a];
        a3 += sAh[j0 + j + 3] * g_Wqt[(j0 + j + 3) * ATT + a];
    }
    sQ[q4 * ATT + a] = (a0 + a1) + (a2 + a3);
    __syncthreads();
    if (t < ATT) g_q[b * ATT + t] = (sQ[t] + sQ[ATT + t]) + (sQ[2 * ATT + t] + sQ[3 * ATT + t]);
    flag_add(&g_fq);
}

__device__ __forceinline__ void att1_phase(const float* __restrict__ W_loc,
                                           const float* __restrict__ b_loc,
                                           const float* __restrict__ Wv,
                                           const int* __restrict__ mem_len,
                                           unsigned fq_target,
                                           float* __restrict__ sh) {
    int bx = blockIdx.x;
    int b = bx & 31, tc = bx >> 5;
    int t = threadIdx.x;
    int tbase = tc * 64;
    float* sAw0 = sh;            // 96
    float* sAw1 = sh + 96;       // 96
    float* sQ   = sh + 192;      // 128
    float* sWl  = sh + 320;      // 1984
    float* sLoc = sh + 2304;     // 64*32
    float* sEp  = sh + 4352;     // 16*16
    for (int i = t; i < 94; i += NTHR) {
        int tt = tbase - 15 + i;
        bool ok = (tt >= 0) && (tt < TENC);
        sAw0[i] = ok ? g_aw[b * TENC + tt] : 0.f;
        sAw1[i] = ok ? g_awc[b * TENC + tt] : 0.f;
    }
    for (int i = t; i < LOCF * 2 * LOCK; i += NTHR) sWl[i] = W_loc[i];
    __syncthreads();
    for (int i = t; i < 64 * LOCF; i += NTHR) {
        int f = i & 31, tt = i >> 5;
        const float* w0 = &sWl[f * 62];
        const float* w1 = &sWl[f * 62 + 31];
        float c0 = b_loc[f], c1 = 0.f, c2 = 0.f, c3 = 0.f;
#pragma unroll
        for (int k = 0; k < 30; k += 2) {
            c0 += sAw0[tt + k] * w0[k];
            c1 += sAw0[tt + k + 1] * w0[k + 1];
            c2 += sAw1[tt + k] * w1[k];
            c3 += sAw1[tt + k + 1] * w1[k + 1];
        }
        c0 += sAw0[tt + 30] * w0[30];
        c2 += sAw1[tt + 30] * w1[30];
        sLoc[tt * 32 + f] = (c0 + c1) + (c2 + c3);
    }
    flag_wait(&g_fq, fq_target);
    if (t < ATT) sQ[t] = g_q[b * ATT + t];
    __syncthreads();
    int a = t & 127;
    int q4 = t >> 7;               // 0..3 -> tt block of 16
    float wld[32];
#pragma unroll
    for (int f = 0; f < 32; f++) wld[f] = g_Wldt[f * ATT + a];
    float wv = Wv[a];
    float qa = sQ[a];
    int lane = t & 31, w = t >> 5;
#pragma unroll 2
    for (int tl = 0; tl < 16; tl++) {
        int tt = q4 * 16 + tl;
        float l0 = 0.f, l1 = 0.f, l2 = 0.f, l3 = 0.f;
#pragma unroll
        for (int f = 0; f < 8; f++) {
            l0 += sLoc[tt * 32 + f]      * wld[f];
            l1 += sLoc[tt * 32 + f + 8]  * wld[f + 8];
            l2 += sLoc[tt * 32 + f + 16] * wld[f + 16];
            l3 += sLoc[tt * 32 + f + 24] * wld[f + 24];
        }
        float lA = (l0 + l1) + (l2 + l3);
        float v = tanhf(qa + g_keys[((size_t)(b * TENC + tbase + tt)) * ATT + a] + lA) * wv;
        for (int off = 16; off; off >>= 1) v += __shfl_down_sync(0xffffffffu, v, off);
        if (lane == 0) sEp[w * 16 + tl] = v;
    }
    __syncthreads();
    int L = mem_len[b];
    for (int tt = t; tt < 64; tt += NTHR) {
        int grp = tt >> 4, tl = tt & 15;
        float e = (sEp[(grp * 4 + 0) * 16 + tl] + sEp[(grp * 4 + 1) * 16 + tl])
                + (sEp[(grp * 4 + 2) * 16 + tl] + sEp[(grp * 4 + 3) * 16 + tl]);
        int tg = tbase + tt;
        g_e[b * TENC + tg] = (tg >= L) ? -1e30f : e;
    }
    flag_add(&g_fe[b]);
}

__device__ __forceinline__ void att2_phase(const float* __restrict__ memory, int b,
                                           float* __restrict__ dout, int tstep,
                                           float* __restrict__ sh) {
    int t = threadIdx.x;
    float* sE = sh;
    float* sR1 = sh + 256;
    float* sR2 = sh + 264;
    if (t < 256) sE[t] = g_e[b * TENC + t];
    __syncthreads();
    float p = 0.f;
    if (t < 256) {
        float v = sE[t];
        for (int off = 16; off; off >>= 1) v = fmaxf(v, __shfl_down_sync(0xffffffffu, v, off));
        if ((t & 31) == 0) sR1[t >> 5] = v;
    }
    __syncthreads();
    if (t < 8) {
        float m = sR1[t];
        for (int off = 4; off; off >>= 1) m = fmaxf(m, __shfl_down_sync(0xffu, m, off));
        if (t == 0) sR1[0] = m;
    }
    __syncthreads();
    if (t < 256) {
        float mx = sR1[0];
        p = expf(sE[t] - mx);
        float sv = p;
        for (int off = 16; off; off >>= 1) sv += __shfl_down_sync(0xffffffffu, sv, off);
        if ((t & 31) == 0) sR2[t >> 5] = sv;
    }
    __syncthreads();
    if (t < 8) {
        float m = sR2[t];
        for (int off = 4; off; off >>= 1) m += __shfl_down_sync(0xffu, m, off);
        if (t == 0) sR2[0] = m;
    }
    __syncthreads();
    if (t < 256) {
        float aw = p / sR2[0];
        sE[t] = aw;
        g_aw[b * TENC + t] = aw;
        g_awc[b * TENC + t] += aw;
        dout[ALIGN_OFF + ((size_t)(b * TDEC + tstep)) * TENC + t] = aw;
    }
    __syncthreads();
    int d = t;   // 0..511 = full EDIM
    float p0 = 0.f, p1 = 0.f, p2 = 0.f, p3 = 0.f;
    for (int tt = 0; tt < TENC; tt += 4) {
        const float* m0 = &memory[((size_t)(b * TENC + tt)) * EDIM + d];
        p0 += sE[tt]     * m0[0];
        p1 += sE[tt + 1] * m0[EDIM];
        p2 += sE[tt + 2] * m0[2 * EDIM];
        p3 += sE[tt + 3] * m0[3 * EDIM];
    }
    float acc = (p0 + p1) + (p2 + p3);
    g_cat_a[b * KA + 256 + d] = acc;
    g_cat_d[b * KD + HID + d] = acc;
    flag_add(&g_fctx);
}

__device__ __forceinline__ void combineD_phase(int b,
                                               const float* __restrict__ W_lin,
                                               const float* __restrict__ b_lin,
                                               const float* __restrict__ W_gate,
                                               const float* __restrict__ b_gate,
                                               float* __restrict__ dout, int tstep,
                                               float* __restrict__ sh) {
    int t = threadIdx.x;
    float* sOut = sh;   // [1536]
#pragma unroll
    for (int u = 0; u < 2; u++) {
        int h = u * 512 + t;
        float zi = g_bd[h], zf = g_bd[HID + h], zg = g_bd[2 * HID + h], zo = g_bd[3 * HID + h];
#pragma unroll
        for (int sp = 0; sp < NSPL; sp++) {
            const float* zp = &g_zpD[((size_t)(sp * B32 + b)) * R4];
            zi += zp[h]; zf += zp[HID + h]; zg += zp[2 * HID + h]; zo += zp[3 * HID + h];
        }
        float c = sigm(zf) * g_dc[b * HID + h] + sigm(zi) * tanhf(zg);
        float hn = sigm(zo) * tanhf(c);
        g_dc[b * HID + h] = c;
        g_cat_d[b * KD + 1536 + h] = hn;
        sOut[h] = hn;
    }
    sOut[HID + t] = g_cat_d[b * KD + HID + t];
    __syncthreads();
    int lane = t & 31, w = t >> 5;
    for (int m = w; m < 81; m += 16) {
        const float* row; float bias;
        if (m < 80) { row = W_lin + (size_t)m * 1536; bias = b_lin[m]; }
        else        { row = W_gate; bias = b_gate[0]; }
        float a0 = 0.f, a1 = 0.f, a2 = 0.f, a3 = 0.f;
        for (int k = lane; k < 1536; k += 128) {
            a0 += sOut[k] * row[k];
            a1 += sOut[k + 32] * row[k + 32];
            a2 += sOut[k + 64] * row[k + 64];
            a3 += sOut[k + 96] * row[k + 96];
        }
        float acc = (a0 + a1) + (a2 + a3);
        for (int off = 16; off; off >>= 1) acc += __shfl_down_sync(0xffffffffu, acc, off);
        if (lane == 0) {
            float r = acc + bias;
            if (m < 80) dout[((size_t)(b * NMELS + m)) * TDEC + tstep] = r;
            else        dout[GATE_OFF + b * TDEC + tstep] = r;
        }
    }
}

__device__ __forceinline__ void xcopy_phase(int b, int tstep) {
    int t = threadIdx.x;
    if (t < PRE) g_cat_a[b * KA + t] = g_X[((size_t)(tstep * B32 + b)) * PRE + t];
}

// ---------------- the single persistent kernel ----------------
__global__ void __launch_bounds__(NTHR) k_steps(
    const float* __restrict__ memory, const float* __restrict__ mel_target,
    const int* __restrict__ mem_len,
    const float* __restrict__ W_p1, const float* __restrict__ b_p1,
    const float* __restrict__ W_p2, const float* __restrict__ b_p2,
    const float* __restrict__ Wih_a, const float* __restrict__ Whh_a,
    const float* __restrict__ bih_a, const float* __restrict__ bhh_a,
    const float* __restrict__ Wq, const float* __restrict__ Wm,
    const float* __restrict__ Wv, const float* __restrict__ W_loc,
    const float* __restrict__ b_loc, const float* __restrict__ W_locd,
    const float* __restrict__ Wih_d, const float* __restrict__ Whh_d,
    const float* __restrict__ bih_d, const float* __restrict__ bhh_d,
    const float* __restrict__ W_lin, const float* __restrict__ b_lin,
    const float* __restrict__ W_gate, const float* __restrict__ b_gate,
    float* __restrict__ dout) {
    __shared__ __align__(16) float sh[10752];
    int bx = blockIdx.x;
    int tid = threadIdx.x;

    // ---- setup S1 (grid-strided) ----
    {
        int gtid = bx * NTHR + tid;
        const int GN = NBLK * NTHR;
        for (int i = gtid; i < B32*KA;   i += GN) g_cat_a[i] = 0.f;
        for (int i = gtid; i < B32*KD;   i += GN) g_cat_d[i] = 0.f;
        for (int i = gtid; i < B32*HID;  i += GN) { g_ac[i] = 0.f; g_dc[i] = 0.f; }
        for (int i = gtid; i < B32*TENC; i += GN) { g_aw[i] = 0.f; g_awc[i] = 0.f; }
        for (int i = gtid; i < R4;       i += GN) { g_ba[i] = bih_a[i] + bhh_a[i]; g_bd[i] = bih_d[i] + bhh_d[i]; }
        for (int i = gtid; i < HID*ATT;  i += GN) { int k = i >> 7, a = i & 127; g_Wqt[i]  = Wq[a*HID + k]; }
        for (int i = gtid; i < EDIM*ATT; i += GN) { int k = i >> 7, a = i & 127; g_Wmt[i]  = Wm[a*EDIM + k]; }
        for (int i = gtid; i < NMELS*PRE;i += GN) { int m = i >> 8, j = i & 255; g_Wp1t[i] = W_p1[j*NMELS + m]; }
        for (int i = gtid; i < PRE*PRE;  i += GN) { int k = i >> 8, j = i & 255; g_Wp2t[i] = W_p2[j*PRE + k]; }
        for (int i = gtid; i < LOCF*ATT; i += GN) { int f = i >> 7, a = i & 127; g_Wldt[i] = W_locd[a*LOCF + f]; }
        for (int i = gtid; i < B32;      i += GN) g_fe[i] = 0u;
        if (gtid == 0) { g_fq = 0u; g_fctx = 0u; g_fgA = 0u; g_fdh = 0u; }
        for (int r = bx; r < R4; r += NBLK) {
            const float* s1 = Wih_a + (size_t)r * 768;
            const float* s2 = Whh_a + (size_t)r * 1024;
            float* dst = g_Wa + (size_t)r * KA;
            for (int k = tid; k < 768; k += NTHR) dst[k] = s1[k];
            for (int k = tid; k < 1024; k += NTHR) dst[768 + k] = s2[k];
        }
        for (int r = bx; r < R4; r += NBLK) {
            const float* s1 = Wih_d + (size_t)r * 1536;
            const float* s2 = Whh_d + (size_t)r * 1024;
            float* dst = g_Wd + (size_t)r * KD;
            for (int k = tid; k < 1536; k += NTHR) dst[k] = s1[k];
            for (int k = tid; k < 1024; k += NTHR) dst[1536 + k] = s2[k];
        }
    }
    gsync();
    // ---- setup S2: keys + prenet ----
    for (int u = bx; u < 512; u += NBLK) keys_unit(memory, u, sh);
    for (int ts = bx; ts < TDEC; ts += NBLK) prenet_unit(mel_target, b_p1, b_p2, ts, sh);
    gsync();

    // ---- main loop (1 gsync/step; everything else flag-gated) ----
    int mtile = bx & 31, s = bx >> 5;
    int mrow0 = mtile * 128;
    int dh0 = 48 + 8 * s, dh1 = dh0 + 8;
    int ah0 = 8 * s,      ah1 = ah0 + 8;
    int cx0 = 32 + 4 * s, cx1 = cx0 + 4;

    for (int tstep = 0; tstep < TDEC; tstep++) {
        unsigned f32t = 32u * (unsigned)(tstep + 1);
        unsigned f128 = 128u * (unsigned)(tstep + 1);

        // GEMM-A (no intra-step waits: cat_a complete since last gsync)
        {
            float acc[4][4];
#pragma unroll
            for (int i = 0; i < 4; i++)
#pragma unroll
                for (int j = 0; j < 4; j++) acc[i][j] = 0.f;
            gemm_chunks<KA>(g_Wa, g_cat_a, mrow0, s * 14, s * 14 + 14, acc, sh);
            zp_store(g_zpA, acc, s, mrow0, sh);
            flag_add(&g_fgA);
        }

        // role-specialized mid work
        if (bx < 32) {
            flag_wait(&g_fgA, f128);
            combineA_phase(bx, sh);                  // releases g_fq
        } else if (bx < 64) {
            if (tstep > 0) {
                combineD_phase(bx - 32, W_lin, b_lin, W_gate, b_gate, dout, tstep - 1, sh);
                flag_add(&g_fdh);
            }
        } else if (bx < 96) {
            flag_wait(&g_fgA, f128);
            if (tstep + 1 < TDEC) xcopy_phase(bx - 64, tstep + 1);
        }
        __syncthreads();

        // attention energies (conv overlaps; waits fq internally; releases fe[b])
        att1_phase(W_loc, b_loc, Wv, mem_len, f32t, sh);

        // att2 on otherwise-idle blocks 96-127
        if (bx >= 96) {
            flag_wait(&g_fe[bx & 31], 4u * (unsigned)(tstep + 1));
            att2_phase(memory, bx & 31, dout, tstep, sh);   // releases g_fctx
        }

        // GEMM-D: dh -> ah -> ctx segments with per-dependency waits
        {
            float acc[4][4];
#pragma unroll
            for (int i = 0; i < 4; i++)
#pragma unroll
                for (int j = 0; j < 4; j++) acc[i][j] = 0.f;
            flag_wait(&g_fdh, 32u * (unsigned)tstep);
            gemm_chunks<KD>(g_Wd, g_cat_d, mrow0, dh0, dh1, acc, sh);
            flag_wait(&g_fq, f32t);
            gemm_chunks<KD>(g_Wd, g_cat_d, mrow0, ah0, ah1, acc, sh);
            flag_wait(&g_fctx, f32t);
            gemm_chunks<KD>(g_Wd, g_cat_d, mrow0, cx0, cx1, acc, sh);
            zp_store(g_zpD, acc, s, mrow0, sh);
        }
        gsync();
    }
    if (bx >= 32 && bx < 64)
        combineD_phase(bx - 32, W_lin, b_lin, W_gate, b_gate, dout, TDEC - 1, sh);
}

// ---------------- host ----------------
extern "C" void kernel_launch(void* const* d_in, const int* in_sizes, int n_in,
                              void* d_out, int out_size) {
    const float* memory   = (const float*)d_in[0];
    const float* mel_tgt  = (const float*)d_in[1];
    const int*   mem_len  = (const int*)  d_in[2];
    const float* W_p1     = (const float*)d_in[3];
    const float* b_p1     = (const float*)d_in[4];
    const float* W_p2     = (const float*)d_in[5];
    const float* b_p2     = (const float*)d_in[6];
    const float* Wih_a    = (const float*)d_in[7];
    const float* Whh_a    = (const float*)d_in[8];
    const float* bih_a    = (const float*)d_in[9];
    const float* bhh_a    = (const float*)d_in[10];
    const float* Wq       = (const float*)d_in[11];
    const float* Wm       = (const float*)d_in[12];
    const float* Wv       = (const float*)d_in[13];
    const float* W_loc    = (const float*)d_in[14];
    const float* b_loc    = (const float*)d_in[15];
    const float* W_locd   = (const float*)d_in[16];
    const float* Wih_d    = (const float*)d_in[17];
    const float* Whh_d    = (const float*)d_in[18];
    const float* bih_d    = (const float*)d_in[19];
    const float* bhh_d    = (const float*)d_in[20];
    const float* W_lin    = (const float*)d_in[21];
    const float* b_lin    = (const float*)d_in[22];
    const float* W_gate   = (const float*)d_in[23];
    const float* b_gate   = (const float*)d_in[24];
    float* out = (float*)d_out;

    k_steps<<<NBLK, NTHR>>>(memory, mel_tgt, mem_len,
                            W_p1, b_p1, W_p2, b_p2,
                            Wih_a, Whh_a, bih_a, bhh_a,
                            Wq, Wm, Wv, W_loc, b_loc, W_locd,
                            Wih_d, Whh_d, bih_d, bhh_d,
                            W_lin, b_lin, W_gate, b_gate, out);
}